// round 1
// baseline (speedup 1.0000x reference)
#include <cuda_runtime.h>

// Problem constants
#define B_  8
#define L_  1024
#define D_  1024
#define H_  16
#define DK_ 64
#define M_  (B_*L_)   // 8192

// Scratch (device globals — allocation-free per harness rules)
__device__ float g_q[B_*H_*L_*DK_];     // [B,H,Lq,dk]
__device__ float g_k[B_*H_*L_*DK_];     // [B,H,Lk,dk]
__device__ float g_v[B_*H_*L_*DK_];     // [B,H,Lk,dk]
__device__ float g_ctx[B_*L_*D_];       // merged [B,Lq,D]
__device__ float g_outs[B_*L_*D_];      // fallback out
__device__ float g_attn[134217728];     // fallback attn [B,H,Lq,Lk]

// ---------------------------------------------------------------------------
// Generic 8192x1024x1024 SGEMM: C = A @ W + bias
// MODE 0: plain row-major C[m*N+n]
// MODE 1: head-split epilogue: C[((b*H+h)*L + l)*64 + d], m=b*L+l, n=h*64+d
// Tile 128x128, BK=8, 256 threads, 8x8 microtile.
// ---------------------------------------------------------------------------
template <int MODE>
__global__ __launch_bounds__(256, 2)
void sgemm8192(const float* __restrict__ A, const float* __restrict__ W,
               const float* __restrict__ bias, float* __restrict__ C)
{
    const int K = D_, N = D_;
    __shared__ float As[8][128];
    __shared__ float Ws[8][128];
    int tid = threadIdx.x;
    int bx = blockIdx.x;     // 0..7  (N/128)
    int by = blockIdx.y;     // 0..63 (M/128)
    int ty = tid >> 4, tx = tid & 15;

    int arow = tid >> 1;            // 0..127
    int ak4  = (tid & 1) << 2;      // 0 or 4
    int wrow = tid >> 5;            // 0..7
    int wcol = (tid & 31) << 2;     // 0..124

    const float* Ap = A + (size_t)(by * 128 + arow) * K + ak4;
    const float* Wp = W + (size_t)wrow * N + bx * 128 + wcol;

    float acc[8][8];
#pragma unroll
    for (int i = 0; i < 8; i++)
#pragma unroll
        for (int j = 0; j < 8; j++) acc[i][j] = 0.f;

    for (int k0 = 0; k0 < K; k0 += 8) {
        float4 a = *(const float4*)(Ap + k0);
        float4 w = *(const float4*)(Wp + (size_t)k0 * N);
        As[ak4 + 0][arow] = a.x;
        As[ak4 + 1][arow] = a.y;
        As[ak4 + 2][arow] = a.z;
        As[ak4 + 3][arow] = a.w;
        *(float4*)&Ws[wrow][wcol] = w;
        __syncthreads();
#pragma unroll
        for (int kk = 0; kk < 8; kk++) {
            float ra[8], rb[8];
            *(float4*)&ra[0] = *(const float4*)&As[kk][ty * 8];
            *(float4*)&ra[4] = *(const float4*)&As[kk][ty * 8 + 4];
            *(float4*)&rb[0] = *(const float4*)&Ws[kk][tx * 8];
            *(float4*)&rb[4] = *(const float4*)&Ws[kk][tx * 8 + 4];
#pragma unroll
            for (int i = 0; i < 8; i++)
#pragma unroll
                for (int j = 0; j < 8; j++) acc[i][j] += ra[i] * rb[j];
        }
        __syncthreads();
    }

    int row0 = by * 128 + ty * 8;
    int col0 = bx * 128 + tx * 8;
#pragma unroll
    for (int i = 0; i < 8; i++) {
#pragma unroll
        for (int j = 0; j < 8; j++) acc[i][j] += bias[col0 + j];
        if (MODE == 0) {
            *(float4*)&C[(size_t)(row0 + i) * N + col0]     = *(float4*)&acc[i][0];
            *(float4*)&C[(size_t)(row0 + i) * N + col0 + 4] = *(float4*)&acc[i][4];
        } else {
            int m = row0 + i;
            int b = m >> 10, l = m & 1023;
            int h = col0 >> 6, d = col0 & 63;   // 8-wide stays within one head
            float* p = &C[(((size_t)(b * H_ + h) * L_ + l) * DK_) + d];
            *(float4*)(p)     = *(float4*)&acc[i][0];
            *(float4*)(p + 4) = *(float4*)&acc[i][4];
        }
    }
}

// ---------------------------------------------------------------------------
// Fused scores + softmax.
// Block = (32 q-rows) x (full 1024 k-cols) for one (b,h).
// S tile fully resident in smem -> attn written to HBM exactly once.
// grid (32 row-tiles, 128 bh), 256 threads.
// ---------------------------------------------------------------------------
__global__ __launch_bounds__(256)
void scores_softmax(const float* __restrict__ Q, const float* __restrict__ Kmat,
                    float* __restrict__ attn)
{
    extern __shared__ float sm[];
    float* Qs   = sm;                    // 32*64
    float* Ks   = Qs + 32 * 64;          // 128*65 (pad -> conflict-free)
    float* Ss   = Ks + 128 * 65;         // 32*1032
    float* sinv = Ss + 32 * 1032;        // 32

    int bh  = blockIdx.y;
    int rt  = blockIdx.x;
    int tid = threadIdx.x;
    const float* Qp = Q    + ((size_t)bh * L_ + rt * 32) * DK_;
    const float* Kp = Kmat + (size_t)bh * L_ * DK_;

    // load Q tile (32x64)
    for (int i = tid; i < 32 * 64 / 4; i += 256)
        ((float4*)Qs)[i] = ((const float4*)Qp)[i];

    int ty = tid >> 5, tx = tid & 31;
    float acc[4][4];

    for (int cc = 0; cc < 8; cc++) {               // 8 chunks of 128 k-cols
        __syncthreads();
        const float* Kc = Kp + (size_t)cc * 128 * DK_;
#pragma unroll
        for (int j = 0; j < 8; j++) {              // 128x64 = 2048 float4
            int idx = tid + j * 256;
            int r = idx >> 4, q = idx & 15;
            float4 v = ((const float4*)Kc)[idx];
            Ks[r * 65 + q * 4 + 0] = v.x;
            Ks[r * 65 + q * 4 + 1] = v.y;
            Ks[r * 65 + q * 4 + 2] = v.z;
            Ks[r * 65 + q * 4 + 3] = v.w;
        }
        __syncthreads();
#pragma unroll
        for (int i = 0; i < 4; i++)
#pragma unroll
            for (int j = 0; j < 4; j++) acc[i][j] = 0.f;
#pragma unroll 16
        for (int d = 0; d < 64; d++) {
            float kv[4];
#pragma unroll
            for (int j = 0; j < 4; j++) kv[j] = Ks[(tx + j * 32) * 65 + d];
#pragma unroll
            for (int i = 0; i < 4; i++) {
                float qv = Qs[(ty * 4 + i) * 64 + d];
#pragma unroll
                for (int j = 0; j < 4; j++) acc[i][j] += qv * kv[j];
            }
        }
#pragma unroll
        for (int i = 0; i < 4; i++)
#pragma unroll
            for (int j = 0; j < 4; j++)
                Ss[(ty * 4 + i) * 1032 + cc * 128 + tx + j * 32] = acc[i][j] * 0.125f;
    }
    __syncthreads();

    // row softmax: 8 threads per row
    int r = tid >> 3, g = tid & 7;
    float m = -1e30f;
    for (int c = g; c < 1024; c += 8) m = fmaxf(m, Ss[r * 1032 + c]);
#pragma unroll
    for (int o = 4; o; o >>= 1) m = fmaxf(m, __shfl_xor_sync(0xffffffffu, m, o));
    float s = 0.f;
    for (int c = g; c < 1024; c += 8) {
        float e = __expf(Ss[r * 1032 + c] - m);
        s += e;
        Ss[r * 1032 + c] = e;
    }
#pragma unroll
    for (int o = 4; o; o >>= 1) s += __shfl_xor_sync(0xffffffffu, s, o);
    if (g == 0) sinv[r] = 1.f / s;
    __syncthreads();

    // coalesced float4 write of normalized attn
    float* Ap = attn + ((size_t)bh * L_ + rt * 32) * L_;
    for (int idx = tid; idx < 32 * 1024 / 4; idx += 256) {
        int rr = idx >> 8;
        int c4 = idx & 255;
        float inv = sinv[rr];
        float4 v;
        v.x = Ss[rr * 1032 + c4 * 4 + 0] * inv;
        v.y = Ss[rr * 1032 + c4 * 4 + 1] * inv;
        v.z = Ss[rr * 1032 + c4 * 4 + 2] * inv;
        v.w = Ss[rr * 1032 + c4 * 4 + 3] * inv;
        ((float4*)Ap)[idx] = v;
    }
}

// ---------------------------------------------------------------------------
// ctx = attn @ V per (b,h): [1024x1024] @ [1024x64] -> merged [B,Lq,D] layout.
// Tile 64(M) x 64(N full) x 32(K), 256 threads, 4x4 microtile.
// ---------------------------------------------------------------------------
__global__ __launch_bounds__(256)
void ctx_gemm(const float* __restrict__ attn, const float* __restrict__ V,
              float* __restrict__ ctx)
{
    __shared__ float As[64][33];
    __shared__ float Vs[32][64];
    int bh = blockIdx.y, mt = blockIdx.x;
    int b = bh >> 4, h = bh & 15;
    int tid = threadIdx.x;
    int ty = tid >> 4, tx = tid & 15;
    const float* Ap = attn + ((size_t)bh * L_ + mt * 64) * L_;
    const float* Vp = V    + (size_t)bh * L_ * DK_;

    float acc[4][4];
#pragma unroll
    for (int i = 0; i < 4; i++)
#pragma unroll
        for (int j = 0; j < 4; j++) acc[i][j] = 0.f;

    for (int k0 = 0; k0 < L_; k0 += 32) {
#pragma unroll
        for (int j = 0; j < 2; j++) {              // A tile 64x32 = 512 float4
            int idx = tid + j * 256;
            int rr = idx >> 3, c4 = idx & 7;
            float4 v = *(const float4*)(Ap + (size_t)rr * L_ + k0 + c4 * 4);
            As[rr][c4 * 4 + 0] = v.x;
            As[rr][c4 * 4 + 1] = v.y;
            As[rr][c4 * 4 + 2] = v.z;
            As[rr][c4 * 4 + 3] = v.w;
        }
#pragma unroll
        for (int j = 0; j < 2; j++) {              // V tile 32x64 = 512 float4
            int idx = tid + j * 256;
            int rr = idx >> 4, c4 = idx & 15;
            *(float4*)&Vs[rr][c4 * 4] = *(const float4*)(Vp + (size_t)(k0 + rr) * DK_ + c4 * 4);
        }
        __syncthreads();
#pragma unroll
        for (int kk = 0; kk < 32; kk++) {
            float4 rb = *(const float4*)&Vs[kk][tx * 4];
#pragma unroll
            for (int i = 0; i < 4; i++) {
                float ra = As[ty * 4 + i][kk];
                acc[i][0] += ra * rb.x;
                acc[i][1] += ra * rb.y;
                acc[i][2] += ra * rb.z;
                acc[i][3] += ra * rb.w;
            }
        }
        __syncthreads();
    }
#pragma unroll
    for (int i = 0; i < 4; i++) {
        size_t off = ((size_t)(b * L_ + mt * 64 + ty * 4 + i)) * D_ + h * DK_ + tx * 4;
        *(float4*)&ctx[off] = *(float4*)&acc[i][0];
    }
}

// ---------------------------------------------------------------------------
extern "C" void kernel_launch(void* const* d_in, const int* in_sizes, int n_in,
                              void* d_out, int out_size)
{
    const float* hidden = (const float*)d_in[0];
    const float* key    = (const float*)d_in[1];
    const float* ctxv   = (const float*)d_in[2];
    const float* Wq = (const float*)d_in[3];
    const float* bq = (const float*)d_in[4];
    const float* Wk = (const float*)d_in[5];
    const float* bk = (const float*)d_in[6];
    const float* Wv = (const float*)d_in[7];
    const float* bv = (const float*)d_in[8];
    const float* Wo = (const float*)d_in[9];
    const float* bo = (const float*)d_in[10];

    float *qp, *kp, *vp, *cp, *ap, *op;
    cudaGetSymbolAddress((void**)&qp, g_q);
    cudaGetSymbolAddress((void**)&kp, g_k);
    cudaGetSymbolAddress((void**)&vp, g_v);
    cudaGetSymbolAddress((void**)&cp, g_ctx);
    cudaGetSymbolAddress((void**)&ap, g_attn);
    cudaGetSymbolAddress((void**)&op, g_outs);

    const size_t out_elems  = (size_t)B_ * L_ * D_;          // 8388608
    const size_t attn_elems = (size_t)B_ * H_ * L_ * L_;      // 134217728

    float* outp;
    float* attnp;
    if ((size_t)out_size >= out_elems + attn_elems) {
        outp  = (float*)d_out;                 // tuple (out, attn), concatenated
        attnp = (float*)d_out + out_elems;
    } else if ((size_t)out_size == attn_elems) {
        outp  = op;                            // attn-only output
        attnp = (float*)d_out;
    } else {
        outp  = (float*)d_out;                 // out-only output
        attnp = ap;
    }

    size_t smem = (size_t)(32 * 64 + 128 * 65 + 32 * 1032 + 32) * sizeof(float); // 173,696 B
    cudaFuncSetAttribute(scores_softmax, cudaFuncAttributeMaxDynamicSharedMemorySize, (int)smem);

    dim3 gproj(8, 64);
    sgemm8192<1><<<gproj, 256>>>(hidden, Wq, bq, qp);
    sgemm8192<1><<<gproj, 256>>>(key,    Wk, bk, kp);
    sgemm8192<1><<<gproj, 256>>>(ctxv,   Wv, bv, vp);

    scores_softmax<<<dim3(32, 128), 256, smem>>>(qp, kp, attnp);

    ctx_gemm<<<dim3(16, 128), 256>>>(attnp, vp, cp);

    sgemm8192<0><<<gproj, 256>>>(cp, Wo, bo, outp);
}

// round 3
// speedup vs baseline: 2.3294x; 2.3294x over previous
#include <cuda_runtime.h>
#include <cuda_bf16.h>
#include <cstdint>

#define B_  8
#define L_  1024
#define D_  1024
#define H_  16
#define DK_ 64
#define M_  (B_*L_)   // 8192

// ---------------- scratch (device globals) ----------------
__device__ __nv_bfloat16 g_qHi[M_*D_], g_qLo[M_*D_];   // [B,H,L,64] layout
__device__ __nv_bfloat16 g_kHi[M_*D_], g_kLo[M_*D_];
__device__ __nv_bfloat16 g_vHi[M_*D_], g_vLo[M_*D_];
__device__ float g_attn[134217728];
__device__ float g_outs[M_*D_];
__device__ __nv_bfloat16 g_hidHi[M_*D_], g_hidLo[M_*D_];
__device__ __nv_bfloat16 g_keyHi[M_*D_], g_keyLo[M_*D_];
__device__ __nv_bfloat16 g_cvHi [M_*D_], g_cvLo [M_*D_];
__device__ __nv_bfloat16 g_ctxHi[M_*D_], g_ctxLo[M_*D_];
__device__ __nv_bfloat16 g_WqHi[D_*D_], g_WqLo[D_*D_];
__device__ __nv_bfloat16 g_WkHi[D_*D_], g_WkLo[D_*D_];
__device__ __nv_bfloat16 g_WvHi[D_*D_], g_WvLo[D_*D_];
__device__ __nv_bfloat16 g_WoHi[D_*D_], g_WoLo[D_*D_];

// ---------------- helpers ----------------
__device__ __forceinline__ uint32_t smem_u32(const void* p) {
    return (uint32_t)__cvta_generic_to_shared((void*)p);
}
#define CP_COMMIT() asm volatile("cp.async.commit_group;" ::: "memory")
#define CP_WAIT0()  asm volatile("cp.async.wait_group 0;" ::: "memory")
#define CP_WAIT1()  asm volatile("cp.async.wait_group 1;" ::: "memory")
__device__ __forceinline__ void cp16(uint32_t dst, const void* src) {
    asm volatile("cp.async.cg.shared.global [%0], [%1], 16;" :: "r"(dst), "l"(src));
}
__device__ __forceinline__ void ldsm4(uint32_t* r, uint32_t a) {
    asm volatile("ldmatrix.sync.aligned.m8n8.x4.shared.b16 {%0,%1,%2,%3}, [%4];"
        : "=r"(r[0]), "=r"(r[1]), "=r"(r[2]), "=r"(r[3]) : "r"(a));
}
__device__ __forceinline__ void ldsm4t(uint32_t* r, uint32_t a) {
    asm volatile("ldmatrix.sync.aligned.m8n8.x4.trans.shared.b16 {%0,%1,%2,%3}, [%4];"
        : "=r"(r[0]), "=r"(r[1]), "=r"(r[2]), "=r"(r[3]) : "r"(a));
}
__device__ __forceinline__ void mma_bf16(float* c, const uint32_t* a, const uint32_t* b) {
    asm volatile("mma.sync.aligned.m16n8k16.row.col.f32.bf16.bf16.f32 "
        "{%0,%1,%2,%3}, {%4,%5,%6,%7}, {%8,%9}, {%0,%1,%2,%3};"
        : "+f"(c[0]), "+f"(c[1]), "+f"(c[2]), "+f"(c[3])
        : "r"(a[0]), "r"(a[1]), "r"(a[2]), "r"(a[3]), "r"(b[0]), "r"(b[1]));
}
__device__ __forceinline__ void hilo_pack(float a, float b, uint32_t& hi, uint32_t& lo) {
    __nv_bfloat16 ha = __float2bfloat16(a), hb = __float2bfloat16(b);
    __nv_bfloat16 la = __float2bfloat16(a - __bfloat162float(ha));
    __nv_bfloat16 lb = __float2bfloat16(b - __bfloat162float(hb));
    hi = (uint32_t)__bfloat16_as_ushort(ha) | ((uint32_t)__bfloat16_as_ushort(hb) << 16);
    lo = (uint32_t)__bfloat16_as_ushort(la) | ((uint32_t)__bfloat16_as_ushort(lb) << 16);
}

// ---------------- prep: fp32 -> bf16 hi/lo ----------------
struct __align__(8) bf4 { __nv_bfloat16 x, y, z, w; };
__global__ void split_kernel(const float4* __restrict__ X,
                             bf4* __restrict__ Hi, bf4* __restrict__ Lo, int n4)
{
    int i = blockIdx.x * 256 + threadIdx.x;
    if (i >= n4) return;
    float4 v = X[i];
    bf4 h, l;
    h.x = __float2bfloat16(v.x); l.x = __float2bfloat16(v.x - __bfloat162float(h.x));
    h.y = __float2bfloat16(v.y); l.y = __float2bfloat16(v.y - __bfloat162float(h.y));
    h.z = __float2bfloat16(v.z); l.z = __float2bfloat16(v.z - __bfloat162float(h.z));
    h.w = __float2bfloat16(v.w); l.w = __float2bfloat16(v.w - __bfloat162float(h.w));
    Hi[i] = h; Lo[i] = l;
}
__global__ void tsplit_kernel(const float* __restrict__ W,
                              __nv_bfloat16* __restrict__ Hi, __nv_bfloat16* __restrict__ Lo)
{
    __shared__ float t[32][33];
    int bx = blockIdx.x * 32, by = blockIdx.y * 32;
    int x = threadIdx.x, y = threadIdx.y;
#pragma unroll
    for (int i = 0; i < 32; i += 8)
        t[y + i][x] = W[(size_t)(by + y + i) * D_ + bx + x];
    __syncthreads();
#pragma unroll
    for (int i = 0; i < 32; i += 8) {
        float v = t[x][y + i];
        __nv_bfloat16 h = __float2bfloat16(v);
        __nv_bfloat16 l = __float2bfloat16(v - __bfloat162float(h));
        size_t o = (size_t)(bx + y + i) * D_ + by + x;
        Hi[o] = h; Lo[o] = l;
    }
}

// ---------------- HMMA GEMM: C[8192,1024] = A @ Bt^T + bias ----------------
// A hi/lo [8192][1024] row-major; Bt hi/lo [1024 n][1024 k].
// Block 128x128, BK=32, 256 threads (2x4 warps, warp 64m x 32n), bf16x3.
// MODE 0: C fp32 row-major. MODE 1: head-split bf16 hi/lo output.
#define HG_ST 40960u   // stage bytes: Ahi|Alo|Bhi|Blo each 128*80
template <int MODE>
__global__ __launch_bounds__(256)
void hgemm(const __nv_bfloat16* __restrict__ AHi, const __nv_bfloat16* __restrict__ ALo,
           const __nv_bfloat16* __restrict__ BHi, const __nv_bfloat16* __restrict__ BLo,
           const float* __restrict__ bias,
           float* __restrict__ C, __nv_bfloat16* __restrict__ CHi, __nv_bfloat16* __restrict__ CLo)
{
    extern __shared__ char smc[];
    const int tid = threadIdx.x, lane = tid & 31, wid = tid >> 5;
    const int wm = wid >> 2, wn = wid & 3;
    const int n0 = blockIdx.x * 128, m0 = blockIdx.y * 128;
    const uint32_t sb = smem_u32(smc);

    const int lr = tid >> 2, lc = tid & 3;        // loader: row, 16B-chunk
    const int arow = wm * 64 + (lane & 15);
    const uint32_t akb = (lane >> 4) * 16;
    const int bn8 = (lane & 16) ? 8 : 0;
    const uint32_t bkh = (lane & 8) ? 16 : 0;
    const int br = lane & 7;

    float acc[4][4][4];
#pragma unroll
    for (int i = 0; i < 4; i++)
#pragma unroll
        for (int j = 0; j < 4; j++)
#pragma unroll
            for (int q = 0; q < 4; q++) acc[i][j][q] = 0.f;

    auto load_stage = [&](int s, int buf) {
        uint32_t base = sb + buf * HG_ST;
        int k0 = s * 32;
#pragma unroll
        for (int half = 0; half < 2; half++) {
            int row = lr + half * 64;
            uint32_t doff = row * 80 + lc * 16;
            cp16(base + doff,          AHi + (size_t)(m0 + row) * D_ + k0 + lc * 8);
            cp16(base + 10240 + doff,  ALo + (size_t)(m0 + row) * D_ + k0 + lc * 8);
            cp16(base + 20480 + doff,  BHi + (size_t)(n0 + row) * D_ + k0 + lc * 8);
            cp16(base + 30720 + doff,  BLo + (size_t)(n0 + row) * D_ + k0 + lc * 8);
        }
    };

    load_stage(0, 0); CP_COMMIT();

    for (int s = 0; s < 32; s++) {
        if (s < 31) { load_stage(s + 1, (s + 1) & 1); CP_COMMIT(); CP_WAIT1(); }
        else        { CP_WAIT0(); }
        __syncthreads();
        uint32_t aHiB = sb + (s & 1) * HG_ST;
        uint32_t aLoB = aHiB + 10240, bHiB = aHiB + 20480, bLoB = aHiB + 30720;
#pragma unroll
        for (int h = 0; h < 2; h++) {
            uint32_t bhi[2][4], blo[2][4];
#pragma unroll
            for (int g = 0; g < 2; g++) {
                uint32_t ba = (uint32_t)(wn * 32 + g * 16 + bn8 + br) * 80 + h * 32 + bkh;
                ldsm4(bhi[g], bHiB + ba);
                ldsm4(blo[g], bLoB + ba);
            }
#pragma unroll
            for (int mf = 0; mf < 4; mf++) {
                uint32_t ah[4], al[4];
                uint32_t aa = (uint32_t)(arow + mf * 16) * 80 + h * 32 + akb;
                ldsm4(ah, aHiB + aa);
                ldsm4(al, aLoB + aa);
#pragma unroll
                for (int g = 0; g < 2; g++)
#pragma unroll
                    for (int j = 0; j < 2; j++) {
                        float* c = acc[mf][g * 2 + j];
                        mma_bf16(c, ah, &bhi[g][j * 2]);
                        mma_bf16(c, ah, &blo[g][j * 2]);
                        mma_bf16(c, al, &bhi[g][j * 2]);
                    }
            }
        }
        __syncthreads();
    }

#pragma unroll
    for (int mf = 0; mf < 4; mf++)
#pragma unroll
        for (int nf = 0; nf < 4; nf++) {
            int col = n0 + wn * 32 + nf * 8 + (lane & 3) * 2;
            float b0 = __ldg(bias + col), b1 = __ldg(bias + col + 1);
            int r0 = m0 + wm * 64 + mf * 16 + (lane >> 2);
#pragma unroll
            for (int half = 0; half < 2; half++) {
                int r = r0 + half * 8;
                float v0 = acc[mf][nf][half * 2 + 0] + b0;
                float v1 = acc[mf][nf][half * 2 + 1] + b1;
                if (MODE == 0) {
                    float2 f2 = make_float2(v0, v1);
                    *(float2*)(C + (size_t)r * D_ + col) = f2;
                } else {
                    int hh = col >> 6, d = col & 63;
                    int bb = r >> 10, l = r & 1023;
                    size_t dst = (((size_t)(bb * H_ + hh) * L_ + l) * DK_) + d;
                    uint32_t hi, lo;
                    hilo_pack(v0, v1, hi, lo);
                    *(uint32_t*)(CHi + dst) = hi;
                    *(uint32_t*)(CLo + dst) = lo;
                }
            }
        }
}

// ---------------- fused scores (HMMA) + softmax ----------------
// Block: 32 q-rows x 1024 k-cols for one (b,h). grid (32, 128), 256 thr.
// smem: Qhi 0 | Qlo 4608 | K[2 bufs](hi,lo) 9216.. | Ss f32 82944 (stride 1032) | sinv 215040
#define SC_SMEM 215168u
__global__ __launch_bounds__(256)
void scores_mma(const __nv_bfloat16* __restrict__ QHi, const __nv_bfloat16* __restrict__ QLo,
                const __nv_bfloat16* __restrict__ KHi, const __nv_bfloat16* __restrict__ KLo,
                float* __restrict__ attn)
{
    extern __shared__ char smc[];
    const int tid = threadIdx.x, lane = tid & 31, wid = tid >> 5;
    const int wm = wid >> 2, wn = wid & 3;
    const int bh = blockIdx.y, q0 = blockIdx.x * 32;
    const uint32_t sb = smem_u32(smc);
    float* Ss = (float*)(smc + 82944);
    float* sinv = (float*)(smc + 215040);

    // Q load (one pass: 32 rows x 8 chunks)
    {
        int row = tid >> 3, ch = tid & 7;
        const size_t src = ((size_t)bh * L_ + q0 + row) * DK_ + ch * 8;
        cp16(sb + row * 144 + ch * 16, QHi + src);
        cp16(sb + 4608 + row * 144 + ch * 16, QLo + src);
    }
    auto loadK = [&](int cc, int buf) {
        uint32_t base = sb + 9216 + buf * 36864;
#pragma unroll
        for (int i = 0; i < 4; i++) {
            int idx = tid + i * 256;
            int row = idx >> 3, ch = idx & 7;
            const size_t src = ((size_t)bh * L_ + cc * 128 + row) * DK_ + ch * 8;
            cp16(base + row * 144 + ch * 16, KHi + src);
            cp16(base + 18432 + row * 144 + ch * 16, KLo + src);
        }
    };
    loadK(0, 0); CP_COMMIT();

    const uint32_t akb = (lane >> 4) * 16;
    const int bn8 = (lane & 16) ? 8 : 0;
    const uint32_t bkh = (lane & 8) ? 16 : 0;
    const int br = lane & 7;

    for (int cc = 0; cc < 8; cc++) {
        if (cc < 7) { loadK(cc + 1, (cc + 1) & 1); CP_COMMIT(); CP_WAIT1(); }
        else        { CP_WAIT0(); }
        __syncthreads();
        uint32_t kHiB = sb + 9216 + (cc & 1) * 36864;
        uint32_t kLoB = kHiB + 18432;
        float acc[4][4];
#pragma unroll
        for (int i = 0; i < 4; i++)
#pragma unroll
            for (int q = 0; q < 4; q++) acc[i][q] = 0.f;
#pragma unroll
        for (int h = 0; h < 4; h++) {
            uint32_t bhi[2][4], blo[2][4];
#pragma unroll
            for (int g = 0; g < 2; g++) {
                uint32_t ba = (uint32_t)(wn * 32 + g * 16 + bn8 + br) * 144 + h * 32 + bkh;
                ldsm4(bhi[g], kHiB + ba);
                ldsm4(blo[g], kLoB + ba);
            }
            uint32_t ah[4], al[4];
            uint32_t aa = (uint32_t)(wm * 16 + (lane & 15)) * 144 + h * 32 + akb;
            ldsm4(ah, sb + aa);
            ldsm4(al, sb + 4608 + aa);
#pragma unroll
            for (int g = 0; g < 2; g++)
#pragma unroll
                for (int j = 0; j < 2; j++) {
                    float* c = acc[g * 2 + j];
                    mma_bf16(c, ah, &bhi[g][j * 2]);
                    mma_bf16(c, ah, &blo[g][j * 2]);
                    mma_bf16(c, al, &bhi[g][j * 2]);
                }
        }
#pragma unroll
        for (int nf = 0; nf < 4; nf++) {
            int col = cc * 128 + wn * 32 + nf * 8 + (lane & 3) * 2;
            int row = wm * 16 + (lane >> 2);
            *(float2*)(Ss + (size_t)row * 1032 + col) =
                make_float2(acc[nf][0] * 0.125f, acc[nf][1] * 0.125f);
            *(float2*)(Ss + (size_t)(row + 8) * 1032 + col) =
                make_float2(acc[nf][2] * 0.125f, acc[nf][3] * 0.125f);
        }
        __syncthreads();
    }

    // softmax: 8 threads per row
    int r = tid >> 3, g = tid & 7;
    float m = -1e30f;
    for (int c = g; c < 1024; c += 8) m = fmaxf(m, Ss[r * 1032 + c]);
#pragma unroll
    for (int o = 4; o; o >>= 1) m = fmaxf(m, __shfl_xor_sync(0xffffffffu, m, o));
    float s = 0.f;
    for (int c = g; c < 1024; c += 8) {
        float e = __expf(Ss[r * 1032 + c] - m);
        s += e;
        Ss[r * 1032 + c] = e;
    }
#pragma unroll
    for (int o = 4; o; o >>= 1) s += __shfl_xor_sync(0xffffffffu, s, o);
    if (g == 0) sinv[r] = 1.f / s;
    __syncthreads();

    float* Ap = attn + ((size_t)bh * L_ + q0) * L_;
    for (int idx = tid; idx < 32 * 1024 / 4; idx += 256) {
        int rr = idx >> 8, c4 = idx & 255;
        float inv = sinv[rr];
        float4 v;
        v.x = Ss[rr * 1032 + c4 * 4 + 0] * inv;
        v.y = Ss[rr * 1032 + c4 * 4 + 1] * inv;
        v.z = Ss[rr * 1032 + c4 * 4 + 2] * inv;
        v.w = Ss[rr * 1032 + c4 * 4 + 3] * inv;
        ((float4*)Ap)[idx] = v;
    }
}

// ---------------- ctx = attn @ V (HMMA), output bf16 hi/lo merged [B,L,D] ----------------
// Block: 128q x 64d, BK=64, grid (8, 128). attn fp32 converted to hi/lo in smem.
// smem: Ahi 0 (128*144) | Alo 18432 | Vhi 36864 (64*144) | Vlo 46080 ; total 55296
__global__ __launch_bounds__(256)
void ctx_mma(const float* __restrict__ attn,
             const __nv_bfloat16* __restrict__ VHi, const __nv_bfloat16* __restrict__ VLo,
             __nv_bfloat16* __restrict__ CHi, __nv_bfloat16* __restrict__ CLo)
{
    extern __shared__ char smc[];
    const int tid = threadIdx.x, lane = tid & 31, wid = tid >> 5;
    const int wm = wid >> 1, wn = wid & 1;
    const int bh = blockIdx.y, q0 = blockIdx.x * 128;
    const int b = bh >> 4, hh = bh & 15;
    const uint32_t sb = smem_u32(smc);

    float acc[2][4][4];
#pragma unroll
    for (int i = 0; i < 2; i++)
#pragma unroll
        for (int j = 0; j < 4; j++)
#pragma unroll
            for (int q = 0; q < 4; q++) acc[i][j][q] = 0.f;

    const uint32_t akb = (lane >> 4) * 16;
    const int vkoff = ((lane & 8) ? 8 : 0) + (lane & 7);
    const int vdoff = (lane & 16) ? 8 : 0;

    for (int k0 = 0; k0 < L_; k0 += 64) {
        // V via cp.async
#pragma unroll
        for (int i = 0; i < 2; i++) {
            int idx = tid + i * 256;
            int row = idx >> 3, ch = idx & 7;
            const size_t src = ((size_t)bh * L_ + k0 + row) * DK_ + ch * 8;
            cp16(sb + 36864 + row * 144 + ch * 16, VHi + src);
            cp16(sb + 46080 + row * 144 + ch * 16, VLo + src);
        }
        CP_COMMIT();
        // attn fp32 -> bf16 hi/lo in smem (manual)
#pragma unroll
        for (int i = 0; i < 4; i++) {
            int task = tid + i * 256;
            int rr = task >> 3, ch = task & 7;
            const float* src = attn + ((size_t)bh * L_ + q0 + rr) * L_ + k0 + ch * 8;
            float4 v0 = *(const float4*)src;
            float4 v1 = *(const float4*)(src + 4);
            uint4 hi, lo;
            hilo_pack(v0.x, v0.y, hi.x, lo.x);
            hilo_pack(v0.z, v0.w, hi.y, lo.y);
            hilo_pack(v1.x, v1.y, hi.z, lo.z);
            hilo_pack(v1.z, v1.w, hi.w, lo.w);
            *(uint4*)(smc + rr * 144 + ch * 16) = hi;
            *(uint4*)(smc + 18432 + rr * 144 + ch * 16) = lo;
        }
        CP_WAIT0();
        __syncthreads();
#pragma unroll
        for (int h = 0; h < 4; h++) {
            uint32_t vhi[2][4], vlo[2][4];
#pragma unroll
            for (int g = 0; g < 2; g++) {
                uint32_t va = (uint32_t)(h * 16 + vkoff) * 144
                            + (uint32_t)(wn * 32 + g * 16 + vdoff) * 2;
                ldsm4t(vhi[g], sb + 36864 + va);
                ldsm4t(vlo[g], sb + 46080 + va);
            }
#pragma unroll
            for (int mf = 0; mf < 2; mf++) {
                uint32_t ah[4], al[4];
                uint32_t aa = (uint32_t)(wm * 32 + mf * 16 + (lane & 15)) * 144 + h * 32 + akb;
                ldsm4(ah, sb + aa);
                ldsm4(al, sb + 18432 + aa);
#pragma unroll
                for (int g = 0; g < 2; g++)
#pragma unroll
                    for (int j = 0; j < 2; j++) {
                        float* c = acc[mf][g * 2 + j];
                        mma_bf16(c, ah, &vhi[g][j * 2]);
                        mma_bf16(c, ah, &vlo[g][j * 2]);
                        mma_bf16(c, al, &vhi[g][j * 2]);
                    }
            }
        }
        __syncthreads();
    }

#pragma unroll
    for (int mf = 0; mf < 2; mf++)
#pragma unroll
        for (int nf = 0; nf < 4; nf++) {
            int d = wn * 32 + nf * 8 + (lane & 3) * 2;
            int q = q0 + wm * 32 + mf * 16 + (lane >> 2);
#pragma unroll
            for (int half = 0; half < 2; half++) {
                int qq = q + half * 8;
                size_t dst = ((size_t)(b * L_ + qq)) * D_ + hh * DK_ + d;
                uint32_t hi, lo;
                hilo_pack(acc[mf][nf][half * 2 + 0], acc[mf][nf][half * 2 + 1], hi, lo);
                *(uint32_t*)(CHi + dst) = hi;
                *(uint32_t*)(CLo + dst) = lo;
            }
        }
}

// ---------------------------------------------------------------------------
extern "C" void kernel_launch(void* const* d_in, const int* in_sizes, int n_in,
                              void* d_out, int out_size)
{
    const float* hidden = (const float*)d_in[0];
    const float* key    = (const float*)d_in[1];
    const float* ctxv   = (const float*)d_in[2];
    const float* Wq = (const float*)d_in[3];
    const float* bq = (const float*)d_in[4];
    const float* Wk = (const float*)d_in[5];
    const float* bk = (const float*)d_in[6];
    const float* Wv = (const float*)d_in[7];
    const float* bv = (const float*)d_in[8];
    const float* Wo = (const float*)d_in[9];
    const float* bo = (const float*)d_in[10];

    float *ap, *op;
    cudaGetSymbolAddress((void**)&ap, g_attn);
    cudaGetSymbolAddress((void**)&op, g_outs);
    __nv_bfloat16 *qHi,*qLo,*kHi,*kLo,*vHi,*vLo;
    cudaGetSymbolAddress((void**)&qHi, g_qHi); cudaGetSymbolAddress((void**)&qLo, g_qLo);
    cudaGetSymbolAddress((void**)&kHi, g_kHi); cudaGetSymbolAddress((void**)&kLo, g_kLo);
    cudaGetSymbolAddress((void**)&vHi, g_vHi); cudaGetSymbolAddress((void**)&vLo, g_vLo);
    __nv_bfloat16 *hidHi,*hidLo,*keyHi,*keyLo,*cvHi,*cvLo,*ctxHi,*ctxLo;
    cudaGetSymbolAddress((void**)&hidHi, g_hidHi); cudaGetSymbolAddress((void**)&hidLo, g_hidLo);
    cudaGetSymbolAddress((void**)&keyHi, g_keyHi); cudaGetSymbolAddress((void**)&keyLo, g_keyLo);
    cudaGetSymbolAddress((void**)&cvHi,  g_cvHi);  cudaGetSymbolAddress((void**)&cvLo,  g_cvLo);
    cudaGetSymbolAddress((void**)&ctxHi, g_ctxHi); cudaGetSymbolAddress((void**)&ctxLo, g_ctxLo);
    __nv_bfloat16 *WqHi,*WqLo,*WkHi,*WkLo,*WvHi,*WvLo,*WoHi,*WoLo;
    cudaGetSymbolAddress((void**)&WqHi, g_WqHi); cudaGetSymbolAddress((void**)&WqLo, g_WqLo);
    cudaGetSymbolAddress((void**)&WkHi, g_WkHi); cudaGetSymbolAddress((void**)&WkLo, g_WkLo);
    cudaGetSymbolAddress((void**)&WvHi, g_WvHi); cudaGetSymbolAddress((void**)&WvLo, g_WvLo);
    cudaGetSymbolAddress((void**)&WoHi, g_WoHi); cudaGetSymbolAddress((void**)&WoLo, g_WoLo);

    const size_t out_elems  = (size_t)B_ * L_ * D_;
    const size_t attn_elems = (size_t)B_ * H_ * L_ * L_;
    float* outp;
    float* attnp;
    if ((size_t)out_size >= out_elems + attn_elems) {
        outp  = (float*)d_out;
        attnp = (float*)d_out + out_elems;
    } else if ((size_t)out_size == attn_elems) {
        outp  = op;
        attnp = (float*)d_out;
    } else {
        outp  = (float*)d_out;
        attnp = ap;
    }

    cudaFuncSetAttribute(hgemm<0>, cudaFuncAttributeMaxDynamicSharedMemorySize, 2 * HG_ST);
    cudaFuncSetAttribute(hgemm<1>, cudaFuncAttributeMaxDynamicSharedMemorySize, 2 * HG_ST);
    cudaFuncSetAttribute(scores_mma, cudaFuncAttributeMaxDynamicSharedMemorySize, SC_SMEM);
    cudaFuncSetAttribute(ctx_mma, cudaFuncAttributeMaxDynamicSharedMemorySize, 55296);

    const int n4 = M_ * D_ / 4;
    split_kernel<<<n4 / 256, 256>>>((const float4*)hidden, (bf4*)hidHi, (bf4*)hidLo, n4);
    split_kernel<<<n4 / 256, 256>>>((const float4*)key,    (bf4*)keyHi, (bf4*)keyLo, n4);
    split_kernel<<<n4 / 256, 256>>>((const float4*)ctxv,   (bf4*)cvHi,  (bf4*)cvLo,  n4);
    tsplit_kernel<<<dim3(32, 32), dim3(32, 8)>>>(Wq, WqHi, WqLo);
    tsplit_kernel<<<dim3(32, 32), dim3(32, 8)>>>(Wk, WkHi, WkLo);
    tsplit_kernel<<<dim3(32, 32), dim3(32, 8)>>>(Wv, WvHi, WvLo);
    tsplit_kernel<<<dim3(32, 32), dim3(32, 8)>>>(Wo, WoHi, WoLo);

    dim3 g(8, 64);
    hgemm<1><<<g, 256, 2 * HG_ST>>>(hidHi, hidLo, WqHi, WqLo, bq, nullptr, qHi, qLo);
    hgemm<1><<<g, 256, 2 * HG_ST>>>(keyHi, keyLo, WkHi, WkLo, bk, nullptr, kHi, kLo);
    hgemm<1><<<g, 256, 2 * HG_ST>>>(cvHi,  cvLo,  WvHi, WvLo, bv, nullptr, vHi, vLo);

    scores_mma<<<dim3(32, 128), 256, SC_SMEM>>>(qHi, qLo, kHi, kLo, attnp);

    ctx_mma<<<dim3(8, 128), 256, 55296>>>(attnp, vHi, vLo, ctxHi, ctxLo);

    hgemm<0><<<g, 256, 2 * HG_ST>>>(ctxHi, ctxLo, WoHi, WoLo, bo, outp, nullptr, nullptr);
}